// round 12
// baseline (speedup 1.0000x reference)
#include <cuda_runtime.h>
#include <cuda_bf16.h>
#include <cstdint>

// LSTM: B=32, T=1024, D=1024, H=128  (gates 4H=512, order i,f,g,o)
// out layout: [B*T*H floats][h_n: B*H][c_n: B*H]

#define B_ 32
#define T_ 1024
#define D_ 1024
#define H_ 128
#define G_ 512
#define GEMM_CTAS 84      // 1 CTA/SM (144KB smem) on the 84 SMs the rec leaves free
#define STAGE_BYTES 49152 // A 16KB + B 32KB per stage, 3 stages

typedef unsigned long long u64;

__device__ __forceinline__ u64 pk2(float x, float y) {
    u64 r;
    asm("mov.b64 %0, {%1, %2};" : "=l"(r)
        : "r"(__float_as_uint(x)), "r"(__float_as_uint(y)));
    return r;
}
__device__ __forceinline__ float2 upk2(u64 v) {
    unsigned lo, hi;
    asm("mov.b64 {%0, %1}, %2;" : "=r"(lo), "=r"(hi) : "l"(v));
    return make_float2(__uint_as_float(lo), __uint_as_float(hi));
}
__device__ __forceinline__ void fma2(u64 &c, u64 a, u64 b) {
    asm("fma.rn.f32x2 %0, %1, %2, %0;" : "+l"(c) : "l"(a), "l"(b));
}
__device__ __forceinline__ float fast_sigmoid(float x) {
    return 1.0f / (1.0f + __expf(-x));
}
__device__ __forceinline__ float fast_tanh(float x) {
    return 1.0f - 2.0f / (__expf(2.0f * x) + 1.0f);
}
__device__ __forceinline__ uint32_t smem_u32(const void* p) {
    uint32_t a;
    asm("{ .reg .u64 t; cvta.to.shared.u64 t, %1; cvt.u32.u64 %0, t; }"
        : "=r"(a) : "l"(p));
    return a;
}
__device__ __forceinline__ void cp16(uint32_t dst, const void* src) {
    asm volatile("cp.async.cg.shared.global [%0], [%1], 16;"
                 :: "r"(dst), "l"(src));
}
__device__ __forceinline__ void ldsm4(uint32_t* r, uint32_t addr) {
    asm volatile("ldmatrix.sync.aligned.m8n8.x4.shared.b16 {%0,%1,%2,%3}, [%4];"
                 : "=r"(r[0]), "=r"(r[1]), "=r"(r[2]), "=r"(r[3]) : "r"(addr));
}
__device__ __forceinline__ void mma16816(float* d, const uint32_t* a,
                                         uint32_t b0, uint32_t b1) {
    asm volatile(
        "mma.sync.aligned.m16n8k16.row.col.f32.bf16.bf16.f32 "
        "{%0,%1,%2,%3}, {%4,%5,%6,%7}, {%8,%9}, {%0,%1,%2,%3};"
        : "+f"(d[0]), "+f"(d[1]), "+f"(d[2]), "+f"(d[3])
        : "r"(a[0]), "r"(a[1]), "r"(a[2]), "r"(a[3]), "r"(b0), "r"(b1));
}

// Scratch (__device__ globals: allocation-free)
__device__ float g_gx[(size_t)B_ * T_ * G_];                 // 64 MB
__device__ __nv_bfloat16 g_A2[(size_t)B_ * T_ * 2048];       // 128 MB  [hi|mid]
__device__ __nv_bfloat16 g_B2[(size_t)G_ * 2048];            // 2 MB    [hi|mid]
__device__ int g_flag[256];   // per m-tile completion counters (target 2)

__global__ void reset_flags() { g_flag[threadIdx.x] = 0; }

// ---------------------------------------------------------------------------
// fp32 -> 2-way bf16 split: hi = rn(x), mid = rn(x - hi); x ~= hi+mid (2^-17)
// ---------------------------------------------------------------------------
__global__ void convert_split2(const float* __restrict__ X,
                               __nv_bfloat16* __restrict__ OUT, int rows)
{
    size_t i = (size_t)blockIdx.x * blockDim.x + threadIdx.x;
    size_t total = (size_t)rows * (D_ / 4);
    if (i >= total) return;
    float4 v = ((const float4*)X)[i];
    size_t m  = i >> 8;
    int   k4  = (int)(i & 255);

    float xs[4] = {v.x, v.y, v.z, v.w};
    __nv_bfloat16 hi[4], md[4];
#pragma unroll
    for (int c = 0; c < 4; c++) {
        hi[c] = __float2bfloat16(xs[c]);
        float r1 = xs[c] - __bfloat162float(hi[c]);
        md[c] = __float2bfloat16(r1);
    }

    __nv_bfloat162* dh = (__nv_bfloat162*)(OUT + m * 2048 + k4 * 4);
    __nv_bfloat162* dm = (__nv_bfloat162*)(OUT + m * 2048 + 1024 + k4 * 4);
    dh[0] = __halves2bfloat162(hi[0], hi[1]);
    dh[1] = __halves2bfloat162(hi[2], hi[3]);
    dm[0] = __halves2bfloat162(md[0], md[1]);
    dm[1] = __halves2bfloat162(md[2], md[3]);
}

// ---------------------------------------------------------------------------
// PERSISTENT bf16 mma.sync GEMM, 3 phases (h,h)(h,m)(m,h).
// CTA tile 128x256, 8 warps @ 64x64, 3-stage cp.async, 1 CTA/SM.
// This round: fragment double-buffering (ldsm for ks+1 overlaps mma of ks)
// and early next-stage cp.async issue (right after the barrier).
// 512 tiles tc-major; 2 n-CTAs bump g_flag[y].
// ---------------------------------------------------------------------------
__global__ __launch_bounds__(256, 1) void gemm_mma_x(
    const __nv_bfloat16* __restrict__ A2, const __nv_bfloat16* __restrict__ B2,
    const float* __restrict__ b1, const float* __restrict__ b2,
    float* __restrict__ GX)
{
    extern __shared__ char smraw[];
    const uint32_t sbase = smem_u32(smraw);

    const int tid = threadIdx.x;
    const int wid = tid >> 5, lid = tid & 31;
    const int wm  = wid >> 2, wn = wid & 3;     // 2 x 4 warp grid, 64x64 tiles
    const int mat = lid >> 3, rin = lid & 7;
    const uint32_t aOff = (uint32_t)((((wm * 8 + (mat & 1)) * 8) + (mat >> 1)) * 128 + rin * 16);
    const uint32_t bOff = 16384u +
        (uint32_t)((((wn * 8 + (mat & 1)) * 8) + (mat >> 1)) * 128 + rin * 16);

    for (int tile = blockIdx.x; tile < 512; tile += gridDim.x) {
        const int y  = tile >> 1;            // m-tile index, tc-major
        const int n0 = (tile & 1) * 256;
        const int bb = y & 31, tc = y >> 5;
        const int m0 = bb * 1024 + tc * 128;

        const char* Ab = (const char*)A2 + (size_t)m0 * 4096;
        const char* Bb = (const char*)B2 + (size_t)n0 * 4096;

        float acc[4][8][4];
#pragma unroll
        for (int i = 0; i < 4; i++)
#pragma unroll
            for (int j = 0; j < 8; j++)
#pragma unroll
                for (int r = 0; r < 4; r++) acc[i][j][r] = 0.0f;

#define ISSUE(kt, st)                                                          \
    do {                                                                       \
        const int ph_ = (kt) >> 4, kk_ = (kt) & 15;                            \
        const int aoff_ = ((ph_ == 2) ? 2048 : 0) + kk_ * 128;                 \
        const int boff_ = ((ph_ == 1) ? 2048 : 0) + kk_ * 128;                 \
        uint32_t dA = sbase + (st) * STAGE_BYTES;                              \
        uint32_t dB = dA + 16384;                                              \
        _Pragma("unroll")                                                      \
        for (int it = 0; it < 4; it++) {                                       \
            int id = tid + it * 256;                                           \
            int mm = id >> 3, kg = id & 7;                                     \
            uint32_t doff = (uint32_t)((((mm >> 3) * 8) + kg) * 128 + (mm & 7) * 16); \
            cp16(dA + doff, Ab + (size_t)mm * 4096 + aoff_ + kg * 16);         \
        }                                                                      \
        _Pragma("unroll")                                                      \
        for (int it = 0; it < 8; it++) {                                       \
            int id = tid + it * 256;                                           \
            int mm = id >> 3, kg = id & 7;                                     \
            uint32_t doff = (uint32_t)((((mm >> 3) * 8) + kg) * 128 + (mm & 7) * 16); \
            cp16(dB + doff, Bb + (size_t)mm * 4096 + boff_ + kg * 16);         \
        }                                                                      \
        asm volatile("cp.async.commit_group;" ::: "memory");                   \
    } while (0)

        ISSUE(0, 0);
        ISSUE(1, 1);

        const int NKT = 48;
        for (int kt = 0; kt < NKT; kt++) {
            const int st = kt % 3;
            if (kt + 1 < NKT) {
                asm volatile("cp.async.wait_group 1;" ::: "memory");
            } else {
                asm volatile("cp.async.wait_group 0;" ::: "memory");
            }
            __syncthreads();   // cp visibility + stage-(kt-1) fully consumed

            // early issue into the just-freed stage: max latency budget
            if (kt + 2 < NKT) ISSUE(kt + 2, (kt + 2) % 3);

            const uint32_t aS = sbase + st * STAGE_BYTES + aOff;
            const uint32_t bS = sbase + st * STAGE_BYTES + bOff;

            // fragment double-buffer: ldsm for ks+1 overlaps mma of ks
            uint32_t af[2][4][4], bf[2][4][4];
#pragma unroll
            for (int i = 0; i < 4; i++) ldsm4(af[0][i], aS + i * 2048);
#pragma unroll
            for (int jp = 0; jp < 4; jp++) ldsm4(bf[0][jp], bS + jp * 2048);
#pragma unroll
            for (int ks = 0; ks < 4; ks++) {
                const int cur = ks & 1, nxt = cur ^ 1;
                if (ks < 3) {
#pragma unroll
                    for (int i = 0; i < 4; i++)
                        ldsm4(af[nxt][i], aS + i * 2048 + (ks + 1) * 256);
#pragma unroll
                    for (int jp = 0; jp < 4; jp++)
                        ldsm4(bf[nxt][jp], bS + jp * 2048 + (ks + 1) * 256);
                }
#pragma unroll
                for (int i = 0; i < 4; i++)
#pragma unroll
                    for (int j = 0; j < 8; j++)
                        mma16816(acc[i][j], af[cur][i],
                                 bf[cur][j >> 1][j & 1], bf[cur][j >> 1][2 + (j & 1)]);
            }
        }

        // Epilogue: bias + store fp32, then signal tile completion
        const int mrow = lid >> 2;
        const int ncol = 2 * (lid & 3);
        float2 bj[8];
#pragma unroll
        for (int j = 0; j < 8; j++) {
            int n = n0 + wn * 64 + j * 8 + ncol;
            bj[j].x = b1[n] + b2[n];
            bj[j].y = b1[n + 1] + b2[n + 1];
        }
#pragma unroll
        for (int i = 0; i < 4; i++) {
            int r0 = m0 + wm * 64 + i * 16 + mrow;
#pragma unroll
            for (int j = 0; j < 8; j++) {
                int n = n0 + wn * 64 + j * 8 + ncol;
                float2 v0 = make_float2(acc[i][j][0] + bj[j].x, acc[i][j][1] + bj[j].y);
                float2 v1 = make_float2(acc[i][j][2] + bj[j].x, acc[i][j][3] + bj[j].y);
                *(float2*)&GX[(size_t)r0 * G_ + n]        = v0;
                *(float2*)&GX[(size_t)(r0 + 8) * G_ + n]  = v1;
            }
        }
        __threadfence();
        __syncthreads();
        if (tid == 0) atomicAdd(&g_flag[y], 1);
    }
}

// ---------------------------------------------------------------------------
// Recurrence v4 (unchanged): per-128-step tile gating on g_flag (target 2),
// boundary-safe gx prefetch, st.async cluster h-exchange.
// ---------------------------------------------------------------------------
__global__ __launch_bounds__(512, 1) __cluster_dims__(2, 1, 1)
void lstm_rec4(const float* __restrict__ GX, const float* __restrict__ Wh,
               float* __restrict__ out, float* __restrict__ hn,
               float* __restrict__ cn)
{
    __shared__ __align__(16) float hbuf[2][128];
    __shared__ __align__(16) float acts[256];
    __shared__ __align__(8) unsigned long long mbar[2];

    const int tid = threadIdx.x;
    uint32_t rank;
    asm("mov.u32 %0, %%cluster_ctarank;" : "=r"(rank));
    const int b    = blockIdx.x >> 1;
    const int rl   = tid >> 1;
    const int p    = tid & 1;
    const int q    = rl >> 6;
    const int j    = rl & 63;
    const int grow = q * 128 + (int)rank * 64 + j;
    const int base = (int)rank * 8;

    u64 wa[16], wb[16];
#pragma unroll
    for (int m = 0; m < 16; m++) {
        int c = p + 2 * ((base + m) & 15);
        float4 w = *(const float4*)&Wh[(size_t)grow * H_ + c * 4];
        wa[m] = pk2(w.x, w.y);
        wb[m] = pk2(w.z, w.w);
    }

    if (tid < 128) { hbuf[0][tid] = 0.0f; hbuf[1][tid] = 0.0f; }
    uint32_t mb_loc0 = smem_u32(&mbar[0]);
    uint32_t mb_loc1 = smem_u32(&mbar[1]);
    if (tid == 0) {
        asm volatile("mbarrier.init.shared.b64 [%0], 1;" :: "r"(mb_loc0) : "memory");
        asm volatile("mbarrier.init.shared.b64 [%0], 1;" :: "r"(mb_loc1) : "memory");
        asm volatile("mbarrier.arrive.expect_tx.shared.b64 _, [%0], 256;" :: "r"(mb_loc0) : "memory");
        asm volatile("mbarrier.arrive.expect_tx.shared.b64 _, [%0], 256;" :: "r"(mb_loc1) : "memory");
    }

    uint32_t ph_peer0, ph_peer1, pm_peer0, pm_peer1;
    {
        const uint32_t r_ = rank ^ 1u;
        int hid = (int)rank * 64 + (tid & 63);
        uint32_t l0 = smem_u32(&hbuf[0][hid]);
        uint32_t l1 = smem_u32(&hbuf[1][hid]);
        asm("mapa.shared::cluster.u32 %0, %1, %2;" : "=r"(ph_peer0) : "r"(l0), "r"(r_));
        asm("mapa.shared::cluster.u32 %0, %1, %2;" : "=r"(ph_peer1) : "r"(l1), "r"(r_));
        asm("mapa.shared::cluster.u32 %0, %1, %2;" : "=r"(pm_peer0) : "r"(mb_loc0), "r"(r_));
        asm("mapa.shared::cluster.u32 %0, %1, %2;" : "=r"(pm_peer1) : "r"(mb_loc1), "r"(r_));
    }

    const float* gxb = GX + (size_t)b * T_ * G_;
    float* outb      = out + (size_t)b * T_ * H_;
    float gxv = 0.0f;
    float cst = 0.0f;
    int ph0 = 0, ph1 = 0;

    asm volatile("barrier.cluster.arrive.aligned;" ::: "memory");
    asm volatile("barrier.cluster.wait.aligned;" ::: "memory");

    for (int t = 0; t < T_; t++) {
        if ((t & 127) == 0) {
            if (tid == 0) {
                const int fidx = (t >> 7) * 32 + b;
                unsigned v;
                do {
                    asm volatile("ld.global.acquire.gpu.u32 %0, [%1];"
                                 : "=r"(v) : "l"((const unsigned*)&g_flag[fidx]) : "memory");
                    if (v < 2u) __nanosleep(128);
                } while (v < 2u);
            }
            __syncthreads();
            if (p == 0) gxv = __ldg(&gxb[(size_t)t * G_ + grow]);
        }

        const int cb = t & 1, nb = cb ^ 1;
        const ulonglong2* h2 = (const ulonglong2*)hbuf[cb];

        u64 acc0 = pk2(0.0f, 0.0f), acc1 = pk2(0.0f, 0.0f);
#pragma unroll
        for (int m = 0; m < 8; m++) {
            ulonglong2 hh = h2[p + 2 * ((base + m) & 15)];
            fma2(acc0, hh.x, wa[m]);
            fma2(acc1, hh.y, wb[m]);
        }
        if (t > 0) {
            uint32_t mb = cb ? mb_loc1 : mb_loc0;
            int par = cb ? ph1 : ph0;
            asm volatile(
                "{\n\t.reg .pred P;\n\t"
                "WL%=:\n\t"
                "mbarrier.try_wait.parity.acquire.cluster.shared::cta.b64 P, [%0], %1, 0x989680;\n\t"
                "@P bra WD%=;\n\t"
                "bra WL%=;\n\t"
                "WD%=:\n\t}"
                :: "r"(mb), "r"(par) : "memory");
            if (cb) ph1 ^= 1; else ph0 ^= 1;
            if (tid == 0)
                asm volatile("mbarrier.arrive.expect_tx.shared.b64 _, [%0], 256;"
                             :: "r"(mb) : "memory");
        }
#pragma unroll
        for (int m = 8; m < 16; m++) {
            ulonglong2 hh = h2[p + 2 * ((base + m) & 15)];
            fma2(acc0, hh.x, wa[m]);
            fma2(acc1, hh.y, wb[m]);
        }
        float2 u0 = upk2(acc0), u1 = upk2(acc1);
        float s = (u0.x + u0.y) + (u1.x + u1.y);
        s += __shfl_xor_sync(0xffffffffu, s, 1);

        if (p == 0) {
            float g = s + gxv;
            acts[rl] = (q == 2) ? fast_tanh(g) : fast_sigmoid(g);
            if (((t + 1) & 127) != 0)
                gxv = __ldg(&gxb[(size_t)(t + 1) * G_ + grow]);
        }
        __syncthreads();

        if (tid < 64) {
            float ig = acts[tid];
            float fg = acts[64 + tid];
            float gg = acts[128 + tid];
            float og = acts[192 + tid];
            cst = fg * cst + ig * gg;
            float hv = og * fast_tanh(cst);
            const int hid = (int)rank * 64 + tid;
            hbuf[nb][hid] = hv;
            {
                uint32_t pa = nb ? ph_peer1 : ph_peer0;
                uint32_t pm = nb ? pm_peer1 : pm_peer0;
                asm volatile(
                    "st.async.shared::cluster.mbarrier::complete_tx::bytes.b32 [%0], %1, [%2];"
                    :: "r"(pa), "r"(__float_as_uint(hv)), "r"(pm) : "memory");
            }
            outb[(size_t)t * H_ + hid] = hv;
            if (t == T_ - 1) {
                hn[b * H_ + hid] = hv;
                cn[b * H_ + hid] = cst;
            }
        }
        __syncthreads();
    }
}

// ---------------------------------------------------------------------------
extern "C" void kernel_launch(void* const* d_in, const int* in_sizes, int n_in,
                              void* d_out, int out_size)
{
    const float* x   = (const float*)d_in[0];
    const float* Wih = (const float*)d_in[1];
    const float* Whh = (const float*)d_in[2];
    const float* bih = (const float*)d_in[3];
    const float* bhh = (const float*)d_in[4];
    float* out = (float*)d_out;

    float* gx = nullptr;
    cudaGetSymbolAddress((void**)&gx, g_gx);
    __nv_bfloat16* A2 = nullptr;
    cudaGetSymbolAddress((void**)&A2, g_A2);
    __nv_bfloat16* B2 = nullptr;
    cudaGetSymbolAddress((void**)&B2, g_B2);

    cudaFuncSetAttribute(gemm_mma_x, cudaFuncAttributeMaxDynamicSharedMemorySize,
                         3 * STAGE_BYTES);

    cudaStream_t s2;
    cudaStreamCreateWithFlags(&s2, cudaStreamNonBlocking);
    cudaEvent_t e0, e1;
    cudaEventCreateWithFlags(&e0, cudaEventDisableTiming);
    cudaEventCreateWithFlags(&e1, cudaEventDisableTiming);

    // main: converts (full chip, before the rec occupies its SMs) + flag reset
    convert_split2<<<(B_ * T_ * (D_ / 4) + 255) / 256, 256>>>(x, A2, B_ * T_);
    convert_split2<<<(G_ * (D_ / 4) + 255) / 256, 256>>>(Wih, B2, G_);
    reset_flags<<<1, 256>>>();

    cudaEventRecord(e0, 0);
    cudaStreamWaitEvent(s2, e0, 0);

    // side stream: persistent GEMM (84 CTAs, 1/SM via 144KB smem)
    gemm_mma_x<<<GEMM_CTAS, 256, 3 * STAGE_BYTES, s2>>>(A2, B2, bih, bhh, gx);
    cudaEventRecord(e1, s2);

    // main: recurrence, gated on flags per 128-step tile
    float* hn = out + (size_t)B_ * T_ * H_;
    float* cn = hn + (size_t)B_ * H_;
    lstm_rec4<<<B_ * 2, 512>>>(gx, Whh, out, hn, cn);

    // join side stream back into the main stream before capture ends
    cudaStreamWaitEvent(0, e1, 0);
}